// round 3
// baseline (speedup 1.0000x reference)
#include <cuda_runtime.h>

// ---------------- problem constants ----------------
#define V_N   7
#define NB    256
#define KTOT  16384      // C*T
#define OE    256
#define MTOT  1792       // NB * V_N
#define H_NSTR 114688    // C*T*V
#define H_CSTR 448       // T*V

// ---------------- GEMM tiling ----------------
#define KSPLIT 8
#define KCHUNK 2048
#define KTILE  32
#define NKT    64        // KCHUNK / KTILE
#define MT     128

// SMEM stage layout (floats)
#define AS_NSTR 232                 // per-n stride of raw A rows (224 data + 8 pad)
#define AS_SZ   (20 * AS_NSTR)      // 4640 floats
#define BF_SZ   (KTILE * OE)        // 8192 floats, fragment-major B
#define BUF_F   (AS_SZ + BF_SZ)     // 12832 floats / stage
#define NSTAGE  4
#define SMEM_BYTES (NSTAGE * BUF_F * 4)   // 205312 B

// ---------------- device scratch ----------------
__device__ float g_Wf[KTOT * OE];            // fragment-major tf32-rounded W
__device__ float g_part[KSPLIT * MTOT * OE]; // K-split partial Wh
__device__ float g_adjn[49];

__device__ __forceinline__ unsigned f2tf(float x) {
    unsigned r;
    asm("cvt.rna.tf32.f32 %0, %1;" : "=r"(r) : "f"(x));
    return r;
}
__device__ __forceinline__ unsigned smem_u32(const void* p) {
    unsigned a;
    asm("{ .reg .u64 t; cvta.to.shared.u64 t, %1; cvt.u32.u64 %0, t; }" : "=r"(a) : "l"(p));
    return a;
}
#define CP_ASYNC_16(dst_u32, src) \
    asm volatile("cp.async.cg.shared.global [%0], [%1], 16;" :: "r"(dst_u32), "l"(src) : "memory")
#define CP_COMMIT() asm volatile("cp.async.commit_group;" ::: "memory")
#define CP_WAIT2()  asm volatile("cp.async.wait_group 2;" ::: "memory")

#define MMA_TF32(c, A, B) \
    asm volatile("mma.sync.aligned.m16n8k8.row.col.f32.tf32.tf32.f32 " \
                 "{%0,%1,%2,%3},{%4,%5,%6,%7},{%8,%9},{%0,%1,%2,%3};\n" \
                 : "+f"(c[0]), "+f"(c[1]), "+f"(c[2]), "+f"(c[3]) \
                 : "r"(A[0]), "r"(A[1]), "r"(A[2]), "r"(A[3]), "r"(B[0]), "r"(B[1]))

// ================= prep: tf32-round W into fragment-major g_Wf =================
// g_Wf[((k/16)*256 + col)*16 + (k&3)*4 + ((k&15)>>2)] = tf32(W[k][col])
__global__ void prep_kernel(const float* __restrict__ W, const float* __restrict__ Bp) {
    __shared__ float s[32 * 260];
    const int t = threadIdx.x;           // 256 threads
    const int k0 = blockIdx.x * 32;      // 512 blocks

    // load 32 rows x 256 cols, round to tf32, stage in smem
#pragma unroll
    for (int i = 0; i < 8; i++) {
        int f4 = t + 256 * i;
        int row = f4 >> 6, c4 = f4 & 63;
        float4 v = *(const float4*)&W[(size_t)(k0 + row) * OE + c4 * 4];
        v.x = __uint_as_float(f2tf(v.x));
        v.y = __uint_as_float(f2tf(v.y));
        v.z = __uint_as_float(f2tf(v.z));
        v.w = __uint_as_float(f2tf(v.w));
        *(float4*)&s[row * 260 + c4 * 4] = v;
    }
    __syncthreads();

    // write two k16-chunks in fragment order (fully coalesced float4 stores)
#pragma unroll
    for (int j = 0; j < 2; j++) {
        float* dst = g_Wf + ((size_t)(k0 >> 4) + j) * 4096;
#pragma unroll
        for (int i = 0; i < 4; i++) {
            int f4 = t + 256 * i;        // 1024 float4 per chunk
            int col = f4 >> 2, t4 = f4 & 3;
            float4 v;
            v.x = s[(j * 16 + 0 + t4) * 260 + col];
            v.y = s[(j * 16 + 4 + t4) * 260 + col];
            v.z = s[(j * 16 + 8 + t4) * 260 + col];
            v.w = s[(j * 16 + 12 + t4) * 260 + col];
            *(float4*)&dst[f4 * 4] = v;
        }
    }

    if (blockIdx.x == 0 && t == 0) {
        float adj[49];
        float mn = 1e30f, mx = -1e30f;
        for (int k = 0; k < 49; k++) {
            float x = Bp[k] + 1e-6f + ((k / 7) == (k % 7) ? 1.0f : 0.0f);
            adj[k] = x;
            mn = fminf(mn, x);
            mx = fmaxf(mx, x);
        }
        float inv = 1.0f / (mx - mn);
        float dsum[7];
        for (int i2 = 0; i2 < 7; i2++) {
            float sum = 0.0f;
            for (int j = 0; j < 7; j++) {
                adj[i2 * 7 + j] = (adj[i2 * 7 + j] - mn) * inv;
                sum += adj[i2 * 7 + j];
            }
            dsum[i2] = sum;
        }
        for (int i2 = 0; i2 < 7; i2++) {
            float di = 1.0f / sqrtf(dsum[i2]);
            for (int j = 0; j < 7; j++)
                g_adjn[i2 * 7 + j] = adj[i2 * 7 + j] * di / sqrtf(dsum[j]);
        }
    }
}

// ================= main GEMM: partial Wh = hf @ W (tf32 mma.sync) =================
__global__ void __launch_bounds__(512, 1) gemm_kernel(const float* __restrict__ h) {
    extern __shared__ float sm[];
    const unsigned smem_base = smem_u32(sm);
    const int tid = threadIdx.x;
    const int ks  = blockIdx.x;
    const int mb  = blockIdx.y;
    const int m0  = mb * MT;
    const int n_first = m0 / 7;
    const int n_last  = (m0 + MT - 1) / 7;
    const int nCnt = n_last - n_first + 1;       // <= 20
    const int kc0 = ks * KCHUNK;

    // ---- staging slot precompute ----
    // B: pure linear copy of 2048 float4 (fragment-major chunk)
    unsigned bdst[4];
    int boff[4];
#pragma unroll
    for (int q = 0; q < 4; q++) {
        int f = tid + q * 512;
        boff[q] = f * 4;
        bdst[q] = (AS_SZ + f * 4) * 4;           // byte offset within stage
    }
    // A: raw gather rows of h (nCnt rows x 224 floats)
    int srcA[3]; unsigned dstA[3];
    bool vA[3];
    const int nA = nCnt * 56;
#pragma unroll
    for (int q = 0; q < 3; q++) {
        int f = tid + q * 512;
        vA[q] = (f < nA);
        int nr = f / 56, s4 = f - nr * 56;
        srcA[q] = (n_first + nr) * H_NSTR + s4 * 4;
        dstA[q] = (unsigned)(nr * AS_NSTR + s4 * 4) * 4;
    }

    // ---- fragment geometry ----
    const int w = tid >> 5, lane = tid & 31;
    const int g = lane >> 2, t4 = lane & 3;
    const int wm = w >> 2, wn = w & 3;           // 4x4 warp grid; warp tile 32(M) x 64(O)
    int baseA[2][2];
#pragma unroll
    for (int mi = 0; mi < 2; mi++)
#pragma unroll
        for (int r = 0; r < 2; r++) {
            int gm = m0 + wm * 32 + mi * 16 + g + r * 8;
            int nn = gm / 7;
            baseA[mi][r] = (nn - n_first) * AS_NSTR + (gm - nn * 7);
        }
    const int bcol0 = wn * 64 + g;               // this thread's first B column

    float acc[2][8][4];
#pragma unroll
    for (int mi = 0; mi < 2; mi++)
#pragma unroll
        for (int ni = 0; ni < 8; ni++)
#pragma unroll
            for (int r = 0; r < 4; r++) acc[mi][ni][r] = 0.0f;

    auto issue = [&](int it) {
        const unsigned sb = smem_base + (unsigned)((it & 3) * BUF_F) * 4;
        const int kt = kc0 + it * KTILE;
        const float* wsrc = g_Wf + (size_t)kt * 256;
#pragma unroll
        for (int q = 0; q < 4; q++) CP_ASYNC_16(sb + bdst[q], wsrc + boff[q]);
        const int hoff = (kt >> 6) * H_CSTR + (kt & 63) * 7;
        const float* hs = h + hoff;
#pragma unroll
        for (int q = 0; q < 3; q++)
            if (vA[q]) CP_ASYNC_16(sb + dstA[q], hs + srcA[q]);
    };

    // ---- prologue: 3 stages in flight ----
    issue(0); CP_COMMIT();
    issue(1); CP_COMMIT();
    issue(2); CP_COMMIT();

    // ---- mainloop: one __syncthreads per k-tile ----
    for (int it = 0; it < NKT; ++it) {
        CP_WAIT2();
        __syncthreads();
        if (it + 3 < NKT) issue(it + 3);
        CP_COMMIT();

        const float* As = sm + (it & 3) * BUF_F;
        const float* Bs = As + AS_SZ;
#pragma unroll
        for (int j = 0; j < 2; j++) {
#pragma unroll
            for (int kk2 = 0; kk2 < 2; kk2++) {
                const int kb = j * 16 + kk2 * 8;
                unsigned Af[2][4];
#pragma unroll
                for (int mi = 0; mi < 2; mi++) {
                    Af[mi][0] = f2tf(As[baseA[mi][0] + (kb + t4) * 7]);
                    Af[mi][1] = f2tf(As[baseA[mi][1] + (kb + t4) * 7]);
                    Af[mi][2] = f2tf(As[baseA[mi][0] + (kb + t4 + 4) * 7]);
                    Af[mi][3] = f2tf(As[baseA[mi][1] + (kb + t4 + 4) * 7]);
                }
                unsigned Bf[8][2];
                const float* bp = Bs + (j * 256 + bcol0) * 16 + t4 * 4 + kk2 * 2;
#pragma unroll
                for (int ni = 0; ni < 8; ni++) {
                    float2 v = *(const float2*)(bp + ni * 128);   // 8 cols * 16 floats
                    Bf[ni][0] = __float_as_uint(v.x);
                    Bf[ni][1] = __float_as_uint(v.y);
                }
#pragma unroll
                for (int mi = 0; mi < 2; mi++)
#pragma unroll
                    for (int ni = 0; ni < 8; ni++) MMA_TF32(acc[mi][ni], Af[mi], Bf[ni]);
            }
        }
    }

    // ---- epilogue: write partial tile ----
    float* op = g_part + ((size_t)ks * MTOT + m0) * OE;
#pragma unroll
    for (int mi = 0; mi < 2; mi++)
#pragma unroll
        for (int ni = 0; ni < 8; ni++) {
            int r = wm * 32 + mi * 16 + g;
            int c = wn * 64 + ni * 8 + 2 * t4;
            float2 v01 = make_float2(acc[mi][ni][0], acc[mi][ni][1]);
            float2 v23 = make_float2(acc[mi][ni][2], acc[mi][ni][3]);
            *(float2*)&op[(size_t)r * OE + c] = v01;
            *(float2*)&op[(size_t)(r + 8) * OE + c] = v23;
        }
}

// ================= tail: reduce partials, attention, epilogue =================
__global__ void tail_kernel(const float* __restrict__ a, float* __restrict__ out) {
    __shared__ float red1[8][7], red2[8][7];
    __shared__ float s1s[7], s2s[7];
    __shared__ float adjn_s[49], att[49], att2[49];

    const int n = blockIdx.x;
    const int o = threadIdx.x;

    float wh[7];
#pragma unroll
    for (int v = 0; v < 7; v++) {
        float s = 0.0f;
#pragma unroll
        for (int ksi = 0; ksi < KSPLIT; ksi++)
            s += g_part[((size_t)ksi * MTOT + n * 7 + v) * OE + o];
        wh[v] = s;
    }
    if (o < 49) adjn_s[o] = g_adjn[o];

    const float a1 = a[o];
    const float a2 = a[OE + o];
    const int wid = o >> 5, lane = o & 31;
#pragma unroll
    for (int v = 0; v < 7; v++) {
        float p1 = wh[v] * a1;
        float p2 = wh[v] * a2;
#pragma unroll
        for (int off = 16; off > 0; off >>= 1) {
            p1 += __shfl_down_sync(0xffffffffu, p1, off);
            p2 += __shfl_down_sync(0xffffffffu, p2, off);
        }
        if (lane == 0) { red1[wid][v] = p1; red2[wid][v] = p2; }
    }
    __syncthreads();
    if (o < 7) {
        float s = 0.0f;
        for (int w2 = 0; w2 < 8; w2++) s += red1[w2][o];
        s1s[o] = s;
    } else if (o >= 32 && o < 39) {
        float s = 0.0f;
        for (int w2 = 0; w2 < 8; w2++) s += red2[w2][o - 32];
        s2s[o - 32] = s;
    }
    __syncthreads();
    if (o < 7) {
        float e[7];
        float mx = -1e30f;
#pragma unroll
        for (int j = 0; j < 7; j++) {
            float x = s1s[o] + s2s[j];
            x = (x >= 0.0f) ? x : 0.2f * x;   // leaky_relu alpha=0.2
            e[j] = x;
            mx = fmaxf(mx, x);
        }
        float sum = 0.0f;
#pragma unroll
        for (int j = 0; j < 7; j++) { e[j] = expf(e[j] - mx); sum += e[j]; }
        float inv = 1.0f / sum;
#pragma unroll
        for (int j = 0; j < 7; j++) att[o * 7 + j] = e[j] * inv;
    }
    __syncthreads();
    if (o < 49) {
        int i = o / 7, kcol = o - i * 7;
        float s = 0.0f;
#pragma unroll
        for (int j = 0; j < 7; j++) s += adjn_s[i * 7 + j] * att[j * 7 + kcol];
        att2[o] = s;
    }
    __syncthreads();
#pragma unroll
    for (int v = 0; v < 7; v++) {
        float s = 0.0f;
#pragma unroll
        for (int j = 0; j < 7; j++) s += att2[v * 7 + j] * wh[j];
        out[((size_t)n * 7 + v) * OE + o] = (s > 0.0f) ? s : expm1f(s);  // elu
    }
}

// ================= launch =================
extern "C" void kernel_launch(void* const* d_in, const int* in_sizes, int n_in,
                              void* d_out, int out_size) {
    const float* h  = (const float*)d_in[0];   // (256,256,64,7)
    const float* W  = (const float*)d_in[1];   // (16384,256)
    const float* a  = (const float*)d_in[2];   // (512,1)
    const float* Bp = (const float*)d_in[3];   // (7,7)
    float* out = (float*)d_out;                // (256,7,256)

    prep_kernel<<<KTOT / 32, 256>>>(W, Bp);

    cudaFuncSetAttribute(gemm_kernel, cudaFuncAttributeMaxDynamicSharedMemorySize, SMEM_BYTES);
    gemm_kernel<<<dim3(KSPLIT, MTOT / MT), 512, SMEM_BYTES>>>(h);

    tail_kernel<<<NB, OE>>>(a, out);
}

// round 4
// speedup vs baseline: 1.6746x; 1.6746x over previous
#include <cuda_runtime.h>
#include <cuda_fp16.h>

// ---------------- problem constants ----------------
#define V_N   7
#define NB    256
#define KTOT  16384      // C*T
#define OE    256
#define MTOT  1792       // NB * V_N
#define H_NSTR 114688    // C*T*V
#define H_CSTR 448       // T*V

// ---------------- GEMM tiling ----------------
#define MT    112        // M rows per CTA (= 16 batch rows exactly)
#define NPB   16         // batch rows per M-block
#define NMB   16         // M blocks (1792/112)
#define KTILE 32
#define NKT_TOTAL 512    // KTOT / KTILE
#define MAXSPLIT 10

// SMEM stage layout
#define AS_NSTR 232                   // floats per n row (224 data + 8 pad)
#define AS_BYTES (NPB * AS_NSTR * 4)  // 14848
#define B_BYTES  (KTILE * OE * 2)     // 16384 (fp16)
#define STAGE_B  (AS_BYTES + B_BYTES) // 31232
#define NSTAGE   4
#define SMEM_BYTES (NSTAGE * STAGE_B) // 124928

// ---------------- device scratch ----------------
__device__ __half g_Wh[KTOT * OE];               // fp16 fragment/swizzled W^T (8.4 MB)
__device__ float  g_part[MAXSPLIT * MTOT * OE];  // K-split partial Wh (18.4 MB)
__device__ float  g_adjn[49];

// ---------------- helpers ----------------
__device__ __forceinline__ unsigned smem_u32(const void* p) {
    unsigned a;
    asm("{ .reg .u64 t; cvta.to.shared.u64 t, %1; cvt.u32.u64 %0, t; }" : "=r"(a) : "l"(p));
    return a;
}
__device__ __forceinline__ unsigned pk2h(float lo, float hi) {
    unsigned r;
    asm("cvt.rn.f16x2.f32 %0, %1, %2;" : "=r"(r) : "f"(hi), "f"(lo));
    return r;
}
#define CP_ASYNC_16(dst_u32, src) \
    asm volatile("cp.async.cg.shared.global [%0], [%1], 16;" :: "r"(dst_u32), "l"(src) : "memory")
#define CP_COMMIT() asm volatile("cp.async.commit_group;" ::: "memory")
#define CP_WAIT2()  asm volatile("cp.async.wait_group 2;" ::: "memory")

#define MMA_F16(c, A, B0, B1) \
    asm volatile("mma.sync.aligned.m16n8k16.row.col.f32.f16.f16.f32 " \
                 "{%0,%1,%2,%3},{%4,%5,%6,%7},{%8,%9},{%0,%1,%2,%3};\n" \
                 : "+f"(c[0]), "+f"(c[1]), "+f"(c[2]), "+f"(c[3]) \
                 : "r"(A[0]), "r"(A[1]), "r"(A[2]), "r"(A[3]), "r"(B0), "r"(B1))

// ================= prep: W (f32 row-major) -> g_Wh (fp16, per-k32 swizzled frag layout) ===
// Per k32-tile (8192 halfs = 16KB): col c owns 32 halfs at [c*32 .. c*32+31],
// arranged as 4 slots of 8B; slot for (t4,kg) lives at index (2*t4+kg)^((c>>1)&1),
// slot content = halfs k = {2t4, 2t4+1, 2t4+8, 2t4+9} + kg*16 (pairs = MMA b0,b1).
__global__ void __launch_bounds__(512) prep_kernel(const float* __restrict__ W,
                                                   const float* __restrict__ Bp) {
    __shared__ float s[32 * 260];
    const int t = threadIdx.x;
    const int k0 = blockIdx.x * 32;       // 512 blocks

#pragma unroll
    for (int i = 0; i < 4; i++) {
        int f4 = t + 512 * i;             // 2048 float4 loads
        int row = f4 >> 6, c4 = f4 & 63;
        float4 v = *(const float4*)&W[(size_t)(k0 + row) * OE + c4 * 4];
        *(float4*)&s[row * 260 + c4 * 4] = v;
    }
    __syncthreads();

#pragma unroll
    for (int i = 0; i < 2; i++) {
        int f4 = t + 512 * i;             // 1024 float4 outputs
        int c = f4 >> 2, t4 = f4 & 3;
        int kb = 2 * t4;
        unsigned p00 = pk2h(s[(kb +  0) * 260 + c], s[(kb +  1) * 260 + c]);
        unsigned p01 = pk2h(s[(kb +  8) * 260 + c], s[(kb +  9) * 260 + c]);
        unsigned p10 = pk2h(s[(kb + 16) * 260 + c], s[(kb + 17) * 260 + c]);
        unsigned p11 = pk2h(s[(kb + 24) * 260 + c], s[(kb + 25) * 260 + c]);
        uint4 o;
        if (((c >> 1) & 1) == 0) o = make_uint4(p00, p01, p10, p11);
        else                     o = make_uint4(p10, p11, p00, p01);
        ((uint4*)g_Wh)[(size_t)blockIdx.x * 1024 + c * 4 + t4] = o;
    }

    if (blockIdx.x == 0 && t == 0) {
        float adj[49];
        float mn = 1e30f, mx = -1e30f;
        for (int k = 0; k < 49; k++) {
            float x = Bp[k] + 1e-6f + ((k / 7) == (k % 7) ? 1.0f : 0.0f);
            adj[k] = x;
            mn = fminf(mn, x);
            mx = fmaxf(mx, x);
        }
        float inv = 1.0f / (mx - mn);
        float dsum[7];
        for (int i2 = 0; i2 < 7; i2++) {
            float sum = 0.0f;
            for (int j = 0; j < 7; j++) {
                adj[i2 * 7 + j] = (adj[i2 * 7 + j] - mn) * inv;
                sum += adj[i2 * 7 + j];
            }
            dsum[i2] = sum;
        }
        for (int i2 = 0; i2 < 7; i2++) {
            float di = 1.0f / sqrtf(dsum[i2]);
            for (int j = 0; j < 7; j++)
                g_adjn[i2 * 7 + j] = adj[i2 * 7 + j] * di / sqrtf(dsum[j]);
        }
    }
}

// ================= main GEMM: partial Wh = hf @ W (fp16 mma.sync, f32 accum) =============
// grid = 148 CTAs: first 4 M-blocks get 10 K-splits, last 12 get 9 (4*10+12*9=148).
__global__ void __launch_bounds__(512, 1) gemm_kernel(const float* __restrict__ h) {
    extern __shared__ float sm[];
    const unsigned smem_base = smem_u32(sm);
    const int tid = threadIdx.x;
    const int bid = blockIdx.x;

    int mb, sp, s_cnt;
    if (bid < 40) { mb = bid / 10; sp = bid - mb * 10; s_cnt = 10; }
    else { int r = bid - 40; mb = 4 + r / 9; sp = r - (mb - 4) * 9; s_cnt = 9; }
    const int base_t = NKT_TOTAL / s_cnt, rem = NKT_TOTAL % s_cnt;
    const int cnt   = base_t + (sp < rem ? 1 : 0);
    const int start = sp * base_t + (sp < rem ? sp : rem);
    const int m0 = mb * MT;
    const int n_first = mb * NPB;

    // ---- staging slots: 896 A float4 + 1024 B 16B-chunks = 1920 ----
    int srcOff[4]; unsigned dstOff[4];
    bool isB[4], valid[4];
#pragma unroll
    for (int q = 0; q < 4; q++) {
        int f = tid + q * 512;
        valid[q] = (f < 1920);
        if (f < 896) {
            int nr = f / 56, s4 = f - nr * 56;
            isB[q] = false;
            srcOff[q] = (n_first + nr) * H_NSTR + s4 * 4;  // float offset (hoff added later)
            dstOff[q] = (unsigned)(nr * AS_NSTR * 4 + s4 * 16);
        } else {
            int b = f - 896;
            isB[q] = true;
            srcOff[q] = b * 8;                              // half offset
            dstOff[q] = (unsigned)(AS_BYTES + b * 16);
        }
    }

    // ---- fragment geometry ----
    const int w = tid >> 5, lane = tid & 31;
    const int g = lane >> 2, t4 = lane & 3;
    const int nu = (w < 12) ? 2 : 1;
    const int un = w & 3;
    int um[2]; int baseA[2][2];
#pragma unroll
    for (int ui = 0; ui < 2; ui++) {
        int u = (ui == 0) ? w : (w + 16);
        um[ui] = u >> 2;
#pragma unroll
        for (int r = 0; r < 2; r++) {
            int m = um[ui] * 16 + g + r * 8;
            int nr = m / 7;
            baseA[ui][r] = nr * AS_NSTR + (m - nr * 7);
        }
    }
    const int xg = (g >> 1) & 1;
    const int s0 = (2 * t4) ^ xg, s1 = (2 * t4 + 1) ^ xg;
    const unsigned bThread = (unsigned)((un * 64 + g) * 64);   // byte offset in B region

    float acc[2][8][4];
#pragma unroll
    for (int ui = 0; ui < 2; ui++)
#pragma unroll
        for (int nt = 0; nt < 8; nt++)
#pragma unroll
            for (int r = 0; r < 4; r++) acc[ui][nt][r] = 0.0f;

    auto issue = [&](int it) {
        const int kt = start + it;
        const unsigned sb = smem_base + (unsigned)((it & 3) * STAGE_B);
        const int hoff = (kt >> 1) * H_CSTR + (kt & 1) * 224;
        const float* ha = h + hoff;
        const __half* wb = g_Wh + (size_t)kt * 8192;
#pragma unroll
        for (int q = 0; q < 4; q++) {
            if (!valid[q]) continue;
            if (isB[q]) CP_ASYNC_16(sb + dstOff[q], wb + srcOff[q]);
            else        CP_ASYNC_16(sb + dstOff[q], ha + srcOff[q]);
        }
    };

    issue(0); CP_COMMIT();
    issue(1); CP_COMMIT();
    issue(2); CP_COMMIT();

    for (int it = 0; it < cnt; ++it) {
        CP_WAIT2();
        __syncthreads();
        if (it + 3 < cnt) issue(it + 3);
        CP_COMMIT();

        const float* As = sm + (it & 3) * (STAGE_B / 4);
        const char*  Bs = (const char*)sm + (it & 3) * STAGE_B + AS_BYTES;

#pragma unroll
        for (int kg = 0; kg < 2; kg++) {
            const int ko = (kg * 16 + 2 * t4) * 7;
            unsigned a[2][4];
            a[0][0] = pk2h(As[baseA[0][0] + ko], As[baseA[0][0] + ko + 7]);
            a[0][1] = pk2h(As[baseA[0][1] + ko], As[baseA[0][1] + ko + 7]);
            a[0][2] = pk2h(As[baseA[0][0] + ko + 56], As[baseA[0][0] + ko + 63]);
            a[0][3] = pk2h(As[baseA[0][1] + ko + 56], As[baseA[0][1] + ko + 63]);
            if (nu == 2) {
                a[1][0] = pk2h(As[baseA[1][0] + ko], As[baseA[1][0] + ko + 7]);
                a[1][1] = pk2h(As[baseA[1][1] + ko], As[baseA[1][1] + ko + 7]);
                a[1][2] = pk2h(As[baseA[1][0] + ko + 56], As[baseA[1][0] + ko + 63]);
                a[1][3] = pk2h(As[baseA[1][1] + ko + 56], As[baseA[1][1] + ko + 63]);
            }
            const unsigned sSlot = (unsigned)((kg ? s1 : s0) * 8);
#pragma unroll
            for (int nt = 0; nt < 8; nt++) {
                uint2 b = *(const uint2*)(Bs + bThread + nt * 512 + sSlot);
                MMA_F16(acc[0][nt], a[0], b.x, b.y);
                if (nu == 2) MMA_F16(acc[1][nt], a[1], b.x, b.y);
            }
        }
    }

    // ---- epilogue ----
    float* op = g_part + ((size_t)sp * MTOT + m0) * OE;
#pragma unroll
    for (int ui = 0; ui < 2; ui++) {
        if (ui >= nu) break;
#pragma unroll
        for (int nt = 0; nt < 8; nt++) {
            int r = um[ui] * 16 + g;
            int c = un * 64 + nt * 8 + 2 * t4;
            *(float2*)&op[(size_t)r * OE + c]       = make_float2(acc[ui][nt][0], acc[ui][nt][1]);
            *(float2*)&op[(size_t)(r + 8) * OE + c] = make_float2(acc[ui][nt][2], acc[ui][nt][3]);
        }
    }
}

// ================= tail: reduce partials, attention, epilogue =================
__global__ void tail_kernel(const float* __restrict__ a, float* __restrict__ out) {
    __shared__ float red1[8][7], red2[8][7];
    __shared__ float s1s[7], s2s[7];
    __shared__ float adjn_s[49], att[49], att2[49];

    const int n = blockIdx.x;
    const int o = threadIdx.x;
    const int s_cnt = ((n >> 4) < 4) ? 10 : 9;   // splits for this n's M-block

    float wh[7];
#pragma unroll
    for (int v = 0; v < 7; v++) {
        float s = 0.0f;
        for (int ksi = 0; ksi < s_cnt; ksi++)
            s += g_part[((size_t)ksi * MTOT + n * 7 + v) * OE + o];
        wh[v] = s;
    }
    if (o < 49) adjn_s[o] = g_adjn[o];

    const float a1 = a[o];
    const float a2 = a[OE + o];
    const int wid = o >> 5, lane = o & 31;
#pragma unroll
    for (int v = 0; v < 7; v++) {
        float p1 = wh[v] * a1;
        float p2 = wh[v] * a2;
#pragma unroll
        for (int off = 16; off > 0; off >>= 1) {
            p1 += __shfl_down_sync(0xffffffffu, p1, off);
            p2 += __shfl_down_sync(0xffffffffu, p2, off);
        }
        if (lane == 0) { red1[wid][v] = p1; red2[wid][v] = p2; }
    }
    __syncthreads();
    if (o < 7) {
        float s = 0.0f;
        for (int w2 = 0; w2 < 8; w2++) s += red1[w2][o];
        s1s[o] = s;
    } else if (o >= 32 && o < 39) {
        float s = 0.0f;
        for (int w2 = 0; w2 < 8; w2++) s += red2[w2][o - 32];
        s2s[o - 32] = s;
    }
    __syncthreads();
    if (o < 7) {
        float e[7];
        float mx = -1e30f;
#pragma unroll
        for (int j = 0; j < 7; j++) {
            float x = s1s[o] + s2s[j];
            x = (x >= 0.0f) ? x : 0.2f * x;
            e[j] = x;
            mx = fmaxf(mx, x);
        }
        float sum = 0.0f;
#pragma unroll
        for (int j = 0; j < 7; j++) { e[j] = expf(e[j] - mx); sum += e[j]; }
        float inv = 1.0f / sum;
#pragma unroll
        for (int j = 0; j < 7; j++) att[o * 7 + j] = e[j] * inv;
    }
    __syncthreads();
    if (o < 49) {
        int i = o / 7, kcol = o - i * 7;
        float s = 0.0f;
#pragma unroll
        for (int j = 0; j < 7; j++) s += adjn_s[i * 7 + j] * att[j * 7 + kcol];
        att2[o] = s;
    }
    __syncthreads();
#pragma unroll
    for (int v = 0; v < 7; v++) {
        float s = 0.0f;
#pragma unroll
        for (int j = 0; j < 7; j++) s += att2[v * 7 + j] * wh[j];
        out[((size_t)n * 7 + v) * OE + o] = (s > 0.0f) ? s : expm1f(s);
    }
}

// ================= launch =================
extern "C" void kernel_launch(void* const* d_in, const int* in_sizes, int n_in,
                              void* d_out, int out_size) {
    const float* h  = (const float*)d_in[0];   // (256,256,64,7)
    const float* W  = (const float*)d_in[1];   // (16384,256)
    const float* a  = (const float*)d_in[2];   // (512,1)
    const float* Bp = (const float*)d_in[3];   // (7,7)
    float* out = (float*)d_out;                // (256,7,256)

    prep_kernel<<<KTOT / 32, 512>>>(W, Bp);

    cudaFuncSetAttribute(gemm_kernel, cudaFuncAttributeMaxDynamicSharedMemorySize, SMEM_BYTES);
    gemm_kernel<<<148, 512, SMEM_BYTES>>>(h);

    tail_kernel<<<NB, OE>>>(a, out);
}

// round 5
// speedup vs baseline: 1.7487x; 1.0443x over previous
#include <cuda_runtime.h>
#include <cuda_fp16.h>

// ---------------- problem constants ----------------
#define V_N   7
#define NB    256
#define KTOT  16384      // C*T
#define OE    256
#define MTOT  1792       // NB * V_N
#define H_NSTR 114688    // C*T*V
#define H_CSTR 448       // T*V

// ---------------- GEMM tiling ----------------
#define MT    112        // M rows per CTA (= 16 batch rows exactly)
#define NPB   16         // batch rows per M-block
#define KTILE 64
#define NKT_TOTAL 256    // KTOT / KTILE
#define MAXSPLIT 10

// SMEM stage layout
#define AS_NSTR 456                   // floats per n row (448 data + 8 pad)
#define AS_BYTES (NPB * AS_NSTR * 4)  // 29184
#define B_BYTES  (KTILE * OE * 2)     // 32768 (fp16)
#define STAGE_B  (AS_BYTES + B_BYTES) // 61952
#define NSTAGE   3
#define SMEM_BYTES (NSTAGE * STAGE_B) // 185856

// ---------------- device scratch ----------------
__device__ __half g_Wh[KTOT * OE];               // fp16 fragment/swizzled W^T (8.4 MB)
__device__ float  g_part[MAXSPLIT * MTOT * OE];  // K-split partial Wh
__device__ float  g_adjn[49];

// ---------------- helpers ----------------
__device__ __forceinline__ unsigned smem_u32(const void* p) {
    unsigned a;
    asm("{ .reg .u64 t; cvta.to.shared.u64 t, %1; cvt.u32.u64 %0, t; }" : "=r"(a) : "l"(p));
    return a;
}
__device__ __forceinline__ unsigned pk2h(float lo, float hi) {
    unsigned r;
    asm("cvt.rn.f16x2.f32 %0, %1, %2;" : "=r"(r) : "f"(hi), "f"(lo));
    return r;
}
#define CP_ASYNC_16(dst_u32, src) \
    asm volatile("cp.async.cg.shared.global [%0], [%1], 16;" :: "r"(dst_u32), "l"(src) : "memory")
#define CP_COMMIT() asm volatile("cp.async.commit_group;" ::: "memory")
#define CP_WAIT1()  asm volatile("cp.async.wait_group 1;" ::: "memory")

#define MMA_F16(c, A, B0, B1) \
    asm volatile("mma.sync.aligned.m16n8k16.row.col.f32.f16.f16.f32 " \
                 "{%0,%1,%2,%3},{%4,%5,%6,%7},{%8,%9},{%0,%1,%2,%3};\n" \
                 : "+f"(c[0]), "+f"(c[1]), "+f"(c[2]), "+f"(c[3]) \
                 : "r"(A[0]), "r"(A[1]), "r"(A[2]), "r"(A[3]), "r"(B0), "r"(B1))

// ================= prep: W (f32 row-major) -> g_Wh (fp16, per-k32 swizzled frag layout) ===
// Per k32-tile (16KB): col c owns 64B; 8 slots of 8B; pair for (t4,kg) at slot
// (2*t4+kg)^((c>>1)&1); slot content = halfs {k, k+1, k+8, k+9}, k = kg*16 + 2*t4.
__global__ void __launch_bounds__(256, 4) prep_kernel(const float* __restrict__ W,
                                                      const float* __restrict__ Bp) {
    __shared__ float s[32 * 260];
    const int t = threadIdx.x;            // 256 threads
    const int k0 = blockIdx.x * 32;       // 512 blocks, one k32-tile each

#pragma unroll
    for (int i = 0; i < 8; i++) {
        int f4 = t + 256 * i;             // 2048 float4 loads
        int row = f4 >> 6, c4 = f4 & 63;
        float4 v = *(const float4*)&W[(size_t)(k0 + row) * OE + c4 * 4];
        *(float4*)&s[row * 260 + c4 * 4] = v;
    }
    __syncthreads();

#pragma unroll
    for (int i = 0; i < 4; i++) {
        int f4 = t + 256 * i;             // 1024 uint4 outputs
        int c = f4 >> 2, t4 = f4 & 3;
        int kb = 2 * t4;
        unsigned p00 = pk2h(s[(kb +  0) * 260 + c], s[(kb +  1) * 260 + c]);
        unsigned p01 = pk2h(s[(kb +  8) * 260 + c], s[(kb +  9) * 260 + c]);
        unsigned p10 = pk2h(s[(kb + 16) * 260 + c], s[(kb + 17) * 260 + c]);
        unsigned p11 = pk2h(s[(kb + 24) * 260 + c], s[(kb + 25) * 260 + c]);
        uint4 o;
        if (((c >> 1) & 1) == 0) o = make_uint4(p00, p01, p10, p11);
        else                     o = make_uint4(p10, p11, p00, p01);
        ((uint4*)g_Wh)[(size_t)blockIdx.x * 1024 + c * 4 + t4] = o;
    }

    if (blockIdx.x == 0 && t == 0) {
        float adj[49];
        float mn = 1e30f, mx = -1e30f;
        for (int k = 0; k < 49; k++) {
            float x = Bp[k] + 1e-6f + ((k / 7) == (k % 7) ? 1.0f : 0.0f);
            adj[k] = x;
            mn = fminf(mn, x);
            mx = fmaxf(mx, x);
        }
        float inv = 1.0f / (mx - mn);
        float dsum[7];
        for (int i2 = 0; i2 < 7; i2++) {
            float sum = 0.0f;
            for (int j = 0; j < 7; j++) {
                adj[i2 * 7 + j] = (adj[i2 * 7 + j] - mn) * inv;
                sum += adj[i2 * 7 + j];
            }
            dsum[i2] = sum;
        }
        for (int i2 = 0; i2 < 7; i2++) {
            float di = 1.0f / sqrtf(dsum[i2]);
            for (int j = 0; j < 7; j++)
                g_adjn[i2 * 7 + j] = adj[i2 * 7 + j] * di / sqrtf(dsum[j]);
        }
    }
}

// ================= main GEMM: partial Wh = hf @ W (fp16 mma.sync, f32 accum) =============
// grid = 148 CTAs: first 4 M-blocks get 10 K-splits, last 12 get 9 (4*10+12*9=148).
__global__ void __launch_bounds__(512, 1) gemm_kernel(const float* __restrict__ h) {
    extern __shared__ float sm[];
    const unsigned smem_base = smem_u32(sm);
    const int tid = threadIdx.x;
    const int bid = blockIdx.x;

    int mb, sp, s_cnt;
    if (bid < 40) { mb = bid / 10; sp = bid - mb * 10; s_cnt = 10; }
    else { int r = bid - 40; mb = 4 + r / 9; sp = r - (mb - 4) * 9; s_cnt = 9; }
    const int base_t = NKT_TOTAL / s_cnt, rem = NKT_TOTAL % s_cnt;
    const int cnt   = base_t + (sp < rem ? 1 : 0);
    const int start = sp * base_t + (sp < rem ? sp : rem);
    const int m0 = mb * MT;
    const int n_first = mb * NPB;

    // ---- staging slots: 1792 A float4 + 2048 B 16B-chunks = 3840 ----
    int srcOff[8]; unsigned dstOff[8];
    bool isB[8], valid[8];
#pragma unroll
    for (int q = 0; q < 8; q++) {
        int f = tid + q * 512;
        valid[q] = (f < 3840);
        if (f < 1792) {
            int nr = f >> 7, s4 = f & 127;               // careful: 112 per row, not 128
            nr = f / 112; s4 = f - nr * 112;
            isB[q] = false;
            srcOff[q] = (n_first + nr) * H_NSTR + s4 * 4;  // float offset (hoff added later)
            dstOff[q] = (unsigned)(nr * AS_NSTR * 4 + s4 * 16);
        } else {
            int b = f - 1792;
            isB[q] = true;
            srcOff[q] = b * 8;                              // half offset within k64 W chunk
            dstOff[q] = (unsigned)(AS_BYTES + b * 16);
        }
    }

    // ---- fragment geometry ----
    const int w = tid >> 5, lane = tid & 31;
    const int g = lane >> 2, t4 = lane & 3;
    const int nu = (w < 12) ? 2 : 1;
    const int un = w & 3;
    int um[2]; int baseA[2][2];
#pragma unroll
    for (int ui = 0; ui < 2; ui++) {
        int u = (ui == 0) ? w : (w + 16);
        um[ui] = u >> 2;
#pragma unroll
        for (int r = 0; r < 2; r++) {
            int m = um[ui] * 16 + g + r * 8;
            int nr = m / 7;
            baseA[ui][r] = nr * AS_NSTR + (m - nr * 7);
        }
    }
    const int xg = (g >> 1) & 1;
    const unsigned bThread = (unsigned)((un * 64 + g) * 64);   // byte offset in B region

    float acc[2][8][4];
#pragma unroll
    for (int ui = 0; ui < 2; ui++)
#pragma unroll
        for (int nt = 0; nt < 8; nt++)
#pragma unroll
            for (int r = 0; r < 4; r++) acc[ui][nt][r] = 0.0f;

    auto issue = [&](int it, int buf) {
        const int kt = start + it;
        const unsigned sb = smem_base + (unsigned)(buf * STAGE_B);
        const float* ha = h + kt * H_CSTR;                  // contiguous 448-float c-row
        const __half* wb = g_Wh + (size_t)kt * 16384;       // two k32-tiles, linear
#pragma unroll
        for (int q = 0; q < 8; q++) {
            if (!valid[q]) continue;
            if (isB[q]) CP_ASYNC_16(sb + dstOff[q], wb + srcOff[q]);
            else        CP_ASYNC_16(sb + dstOff[q], ha + srcOff[q]);
        }
    };

    issue(0, 0); CP_COMMIT();
    issue(1, 1); CP_COMMIT();

    int buf = 0, buf2 = 2;
    for (int it = 0; it < cnt; ++it) {
        CP_WAIT1();
        __syncthreads();
        if (it + 2 < cnt) issue(it + 2, buf2);
        CP_COMMIT();

        const float* As = sm + buf * (STAGE_B / 4);
        const char*  Bs = (const char*)sm + buf * STAGE_B + AS_BYTES;

#pragma unroll
        for (int kg = 0; kg < 4; kg++) {
            const int ko = (kg * 16 + 2 * t4) * 7;
            unsigned a[2][4];
            a[0][0] = pk2h(As[baseA[0][0] + ko],      As[baseA[0][0] + ko + 7]);
            a[0][1] = pk2h(As[baseA[0][1] + ko],      As[baseA[0][1] + ko + 7]);
            a[0][2] = pk2h(As[baseA[0][0] + ko + 56], As[baseA[0][0] + ko + 63]);
            a[0][3] = pk2h(As[baseA[0][1] + ko + 56], As[baseA[0][1] + ko + 63]);
            if (nu == 2) {
                a[1][0] = pk2h(As[baseA[1][0] + ko],      As[baseA[1][0] + ko + 7]);
                a[1][1] = pk2h(As[baseA[1][1] + ko],      As[baseA[1][1] + ko + 7]);
                a[1][2] = pk2h(As[baseA[1][0] + ko + 56], As[baseA[1][0] + ko + 63]);
                a[1][3] = pk2h(As[baseA[1][1] + ko + 56], As[baseA[1][1] + ko + 63]);
            }
            const char* bbase = Bs + (kg >> 1) * 16384 +
                                (unsigned)((((2 * t4 + (kg & 1)) ^ xg)) * 8) + bThread;
#pragma unroll
            for (int nt = 0; nt < 8; nt++) {
                uint2 b = *(const uint2*)(bbase + nt * 512);
                MMA_F16(acc[0][nt], a[0], b.x, b.y);
                if (nu == 2) MMA_F16(acc[1][nt], a[1], b.x, b.y);
            }
        }
        buf = (buf == 2) ? 0 : buf + 1;
        buf2 = (buf2 == 2) ? 0 : buf2 + 1;
    }

    // ---- epilogue ----
    float* op = g_part + ((size_t)sp * MTOT + m0) * OE;
#pragma unroll
    for (int ui = 0; ui < 2; ui++) {
        if (ui >= nu) break;
#pragma unroll
        for (int nt = 0; nt < 8; nt++) {
            int r = um[ui] * 16 + g;
            int c = un * 64 + nt * 8 + 2 * t4;
            *(float2*)&op[(size_t)r * OE + c]       = make_float2(acc[ui][nt][0], acc[ui][nt][1]);
            *(float2*)&op[(size_t)(r + 8) * OE + c] = make_float2(acc[ui][nt][2], acc[ui][nt][3]);
        }
    }
}

// ================= tail: reduce partials, attention, epilogue =================
__global__ void tail_kernel(const float* __restrict__ a, float* __restrict__ out) {
    __shared__ float red1[8][7], red2[8][7];
    __shared__ float s1s[7], s2s[7];
    __shared__ float adjn_s[49], att[49], att2[49];

    const int n = blockIdx.x;
    const int o = threadIdx.x;
    const int s_cnt = ((n >> 4) < 4) ? 10 : 9;

    float wh[7];
#pragma unroll
    for (int v = 0; v < 7; v++) {
        float s = 0.0f;
        for (int ksi = 0; ksi < s_cnt; ksi++)
            s += g_part[((size_t)ksi * MTOT + n * 7 + v) * OE + o];
        wh[v] = s;
    }
    if (o < 49) adjn_s[o] = g_adjn[o];

    const float a1 = a[o];
    const float a2 = a[OE + o];
    const int wid = o >> 5, lane = o & 31;
#pragma unroll
    for (int v = 0; v < 7; v++) {
        float p1 = wh[v] * a1;
        float p2 = wh[v] * a2;
#pragma unroll
        for (int off = 16; off > 0; off >>= 1) {
            p1 += __shfl_down_sync(0xffffffffu, p1, off);
            p2 += __shfl_down_sync(0xffffffffu, p2, off);
        }
        if (lane == 0) { red1[wid][v] = p1; red2[wid][v] = p2; }
    }
    __syncthreads();
    if (o < 7) {
        float s = 0.0f;
        for (int w2 = 0; w2 < 8; w2++) s += red1[w2][o];
        s1s[o] = s;
    } else if (o >= 32 && o < 39) {
        float s = 0.0f;
        for (int w2 = 0; w2 < 8; w2++) s += red2[w2][o - 32];
        s2s[o - 32] = s;
    }
    __syncthreads();
    if (o < 7) {
        float e[7];
        float mx = -1e30f;
#pragma unroll
        for (int j = 0; j < 7; j++) {
            float x = s1s[o] + s2s[j];
            x = (x >= 0.0f) ? x : 0.2f * x;
            e[j] = x;
            mx = fmaxf(mx, x);
        }
        float sum = 0.0f;
#pragma unroll
        for (int j = 0; j < 7; j++) { e[j] = expf(e[j] - mx); sum += e[j]; }
        float inv = 1.0f / sum;
#pragma unroll
        for (int j = 0; j < 7; j++) att[o * 7 + j] = e[j] * inv;
    }
    __syncthreads();
    if (o < 49) {
        int i = o / 7, kcol = o - i * 7;
        float s = 0.0f;
#pragma unroll
        for (int j = 0; j < 7; j++) s += adjn_s[i * 7 + j] * att[j * 7 + kcol];
        att2[o] = s;
    }
    __syncthreads();
#pragma unroll
    for (int v = 0; v < 7; v++) {
        float s = 0.0f;
#pragma unroll
        for (int j = 0; j < 7; j++) s += att2[v * 7 + j] * wh[j];
        out[((size_t)n * 7 + v) * OE + o] = (s > 0.0f) ? s : expm1f(s);
    }
}

// ================= launch =================
extern "C" void kernel_launch(void* const* d_in, const int* in_sizes, int n_in,
                              void* d_out, int out_size) {
    const float* h  = (const float*)d_in[0];   // (256,256,64,7)
    const float* W  = (const float*)d_in[1];   // (16384,256)
    const float* a  = (const float*)d_in[2];   // (512,1)
    const float* Bp = (const float*)d_in[3];   // (7,7)
    float* out = (float*)d_out;                // (256,7,256)

    prep_kernel<<<KTOT / 32, 256>>>(W, Bp);

    cudaFuncSetAttribute(gemm_kernel, cudaFuncAttributeMaxDynamicSharedMemorySize, SMEM_BYTES);
    gemm_kernel<<<148, 512, SMEM_BYTES>>>(h);

    tail_kernel<<<NB, OE>>>(a, out);
}